// round 14
// baseline (speedup 1.0000x reference)
#include <cuda_runtime.h>
#include <cuda_bf16.h>
#include <math.h>
#include <stdint.h>

// Problem constants
constexpr int SEQ   = 1024;
constexpr int DM    = 1024;
constexpr int NHEAD = 16;
constexpr int HDIM  = 64;
constexpr int NB    = 4;
constexpr int MR    = NB * SEQ;

// ---------------- scratch (device globals; no allocation allowed) ----------
__device__ int g_maskflag;

__device__ __nv_bfloat16 g_yh[(size_t)MR * DM];
__device__ __nv_bfloat16 g_yl[(size_t)MR * DM];
__device__ __nv_bfloat16 g_xh[(size_t)MR * DM];
__device__ __nv_bfloat16 g_xl[(size_t)MR * DM];
__device__ __nv_bfloat16 g_qh[(size_t)MR * DM];
__device__ __nv_bfloat16 g_ql[(size_t)MR * DM];
__device__ __nv_bfloat16 g_kh[(size_t)MR * DM];
__device__ __nv_bfloat16 g_kl[(size_t)MR * DM];
__device__ __nv_bfloat16 g_vh[(size_t)MR * DM];
__device__ __nv_bfloat16 g_vl[(size_t)MR * DM];
__device__ __nv_bfloat16 g_vth[(size_t)MR * DM];   // v^T per (b,h): [b][h][d][j]
__device__ __nv_bfloat16 g_vtl[(size_t)MR * DM];
__device__ __nv_bfloat16 g_avh[(size_t)MR * DM];
__device__ __nv_bfloat16 g_avl[(size_t)MR * DM];
__device__ __nv_bfloat16 g_atth[(size_t)NHEAD * SEQ * SEQ];
__device__ __nv_bfloat16 g_attl[(size_t)NHEAD * SEQ * SEQ];
__device__ __nv_bfloat16 g_wqh[(size_t)DM * DM];
__device__ __nv_bfloat16 g_wql[(size_t)DM * DM];
__device__ __nv_bfloat16 g_wkh[(size_t)DM * DM];
__device__ __nv_bfloat16 g_wkl[(size_t)DM * DM];
__device__ __nv_bfloat16 g_wvh[(size_t)DM * DM];
__device__ __nv_bfloat16 g_wvl[(size_t)DM * DM];
__device__ __nv_bfloat16 g_woh[(size_t)DM * DM];
__device__ __nv_bfloat16 g_wol[(size_t)DM * DM];

// ===========================================================================
// helpers
// ===========================================================================
__device__ __forceinline__ uint32_t smem_u32(const void* p) {
    uint32_t r;
    asm("{ .reg .u64 t; cvta.to.shared.u64 t, %1; cvt.u32.u64 %0, t; }"
        : "=r"(r) : "l"(p));
    return r;
}
__device__ __forceinline__ void cp16(uint32_t dst, const void* src) {
    asm volatile("cp.async.cg.shared.global [%0], [%1], 16;" :: "r"(dst), "l"(src));
}
__device__ __forceinline__ void cp_commit() {
    asm volatile("cp.async.commit_group;" ::: "memory");
}
template <int N>
__device__ __forceinline__ void cp_wait() {
    asm volatile("cp.async.wait_group %0;" :: "n"(N) : "memory");
}
__device__ __forceinline__ void ldsm_x4(uint32_t* r, uint32_t addr) {
    asm volatile("ldmatrix.sync.aligned.m8n8.x4.shared.b16 {%0,%1,%2,%3}, [%4];"
        : "=r"(r[0]), "=r"(r[1]), "=r"(r[2]), "=r"(r[3]) : "r"(addr));
}
__device__ __forceinline__ void mma16816(
    float* d, const uint32_t* a, const uint32_t* b)
{
    asm volatile(
        "mma.sync.aligned.m16n8k16.row.col.f32.bf16.bf16.f32 "
        "{%0,%1,%2,%3}, {%4,%5,%6,%7}, {%8,%9}, {%0,%1,%2,%3};"
        : "+f"(d[0]), "+f"(d[1]), "+f"(d[2]), "+f"(d[3])
        : "r"(a[0]), "r"(a[1]), "r"(a[2]), "r"(a[3]), "r"(b[0]), "r"(b[1]));
}

// ===========================================================================
// combined fp32 -> bf16 hi/lo split for the 6 input tensors (1 launch)
// also zeroes the mask flag (blockIdx 0, tid 0).
// ===========================================================================
__global__ __launch_bounds__(256) void split6_kernel(
    const float* __restrict__ y,  __nv_bfloat16* yh, __nv_bfloat16* yl,
    const float* __restrict__ x,  __nv_bfloat16* xh, __nv_bfloat16* xl,
    const float* __restrict__ wq, __nv_bfloat16* qh, __nv_bfloat16* ql,
    const float* __restrict__ wk, __nv_bfloat16* kh, __nv_bfloat16* kl,
    const float* __restrict__ wv, __nv_bfloat16* vh, __nv_bfloat16* vl,
    const float* __restrict__ wo, __nv_bfloat16* oh, __nv_bfloat16* ol,
    int* flag)
{
    if (blockIdx.x == 0 && blockIdx.y == 0 && threadIdx.x == 0) *flag = 0;
    const int seg = blockIdx.y;
    const float* in; __nv_bfloat16 *hi, *lo; int n4;
    switch (seg) {
        case 0:  in = y;  hi = yh; lo = yl; n4 = MR * DM / 4; break;
        case 1:  in = x;  hi = xh; lo = xl; n4 = MR * DM / 4; break;
        case 2:  in = wq; hi = qh; lo = ql; n4 = DM * DM / 4; break;
        case 3:  in = wk; hi = kh; lo = kl; n4 = DM * DM / 4; break;
        case 4:  in = wv; hi = vh; lo = vl; n4 = DM * DM / 4; break;
        default: in = wo; hi = oh; lo = ol; n4 = DM * DM / 4; break;
    }
    int i = blockIdx.x * blockDim.x + threadIdx.x;
    if (i >= n4) return;
    float4 v = ((const float4*)in)[i];
    __nv_bfloat16 h0 = __float2bfloat16(v.x);
    __nv_bfloat16 h1 = __float2bfloat16(v.y);
    __nv_bfloat16 h2 = __float2bfloat16(v.z);
    __nv_bfloat16 h3 = __float2bfloat16(v.w);
    ushort4 H, L;
    H.x = __bfloat16_as_ushort(h0); H.y = __bfloat16_as_ushort(h1);
    H.z = __bfloat16_as_ushort(h2); H.w = __bfloat16_as_ushort(h3);
    L.x = __bfloat16_as_ushort(__float2bfloat16(v.x - __bfloat162float(h0)));
    L.y = __bfloat16_as_ushort(__float2bfloat16(v.y - __bfloat162float(h1)));
    L.z = __bfloat16_as_ushort(__float2bfloat16(v.z - __bfloat162float(h2)));
    L.w = __bfloat16_as_ushort(__float2bfloat16(v.w - __bfloat162float(h3)));
    ((ushort4*)hi)[i] = H;
    ((ushort4*)lo)[i] = L;
}

// ===========================================================================
// mask nonzero check -> flag
// ===========================================================================
__global__ __launch_bounds__(256) void maskchk_kernel(
    const float* __restrict__ mask, int* flag)
{
    int i = blockIdx.x * blockDim.x + threadIdx.x;   // SEQ*SEQ/4 elements
    float4 v = ((const float4*)mask)[i];
    bool nz = (v.x != 0.f) | (v.y != 0.f) | (v.z != 0.f) | (v.w != 0.f);
    if (__syncthreads_or(nz)) {
        if (threadIdx.x == 0) atomicOr(flag, 1);
    }
}

// ===========================================================================
// bf16 transpose of v hi/lo:  vt[b][h][d][j] = v[b*S+j][h*64+d]
// ===========================================================================
__global__ __launch_bounds__(256) void transpose_v_kernel(
    const __nv_bfloat16* __restrict__ vh, const __nv_bfloat16* __restrict__ vl,
    __nv_bfloat16* __restrict__ vth, __nv_bfloat16* __restrict__ vtl)
{
    __shared__ uint16_t th[64][72];
    __shared__ uint16_t tl[64][72];
    const int bh = blockIdx.y;
    const int b  = bh >> 4;
    const int h  = bh & 15;
    const int j0 = blockIdx.x * 64;
    const int tid = threadIdx.x;

#pragma unroll
    for (int i = 0; i < 4; i++) {
        int idx = tid + i * 256;
        int j   = idx >> 4;
        int dq  = (idx & 15) * 4;
        size_t off = (size_t)(b * SEQ + j0 + j) * DM + h * HDIM + dq;
        ushort4 a = *(const ushort4*)((const uint16_t*)vh + off);
        ushort4 c = *(const ushort4*)((const uint16_t*)vl + off);
        th[dq + 0][j] = a.x; th[dq + 1][j] = a.y; th[dq + 2][j] = a.z; th[dq + 3][j] = a.w;
        tl[dq + 0][j] = c.x; tl[dq + 1][j] = c.y; tl[dq + 2][j] = c.z; tl[dq + 3][j] = c.w;
    }
    __syncthreads();

    const int d  = tid >> 2;
    const int jq = (tid & 3) * 16;
    uint16_t* oh = (uint16_t*)vth + ((size_t)bh * HDIM + d) * SEQ + j0 + jq;
    uint16_t* ol = (uint16_t*)vtl + ((size_t)bh * HDIM + d) * SEQ + j0 + jq;
#pragma unroll
    for (int c = 0; c < 4; c++) {
        ushort4 A, B;
        A.x = th[d][jq + c * 4 + 0]; A.y = th[d][jq + c * 4 + 1];
        A.z = th[d][jq + c * 4 + 2]; A.w = th[d][jq + c * 4 + 3];
        B.x = tl[d][jq + c * 4 + 0]; B.y = tl[d][jq + c * 4 + 1];
        B.z = tl[d][jq + c * 4 + 2]; B.w = tl[d][jq + c * 4 + 3];
        *(ushort4*)(oh + c * 4) = A;
        *(ushort4*)(ol + c * 4) = B;
    }
}

// ===========================================================================
// Generic bf16x3 compensated GEMM, ldmatrix fragments, cp.async 2-stage.
// (unchanged from R11 winner)
// ===========================================================================
#define SMM_STRIDE 40   // 32 k elems + 8 pad (bf16)

template <int NT, bool SPLIT_OUT>
__global__ __launch_bounds__(256, 2) void mm3_kernel(
    const __nv_bfloat16* __restrict__ Ah, const __nv_bfloat16* __restrict__ Al,
    size_t asb, size_t ash, int lda,
    const __nv_bfloat16* __restrict__ Wh, const __nv_bfloat16* __restrict__ Wl,
    size_t wsb, size_t wsh, int ldw,
    const float* __restrict__ bias,
    float* __restrict__ C, __nv_bfloat16* __restrict__ Ch, __nv_bfloat16* __restrict__ Cl,
    size_t csb, size_t csh, int ldc,
    int K, float scale)
{
    constexpr int NATOMS  = NT / 16;
    constexpr int A_BYTES = 128 * SMM_STRIDE * 2;
    constexpr int W_BYTES = NT * SMM_STRIDE * 2;
    constexpr int STAGE   = 2 * A_BYTES + 2 * W_BYTES;

    extern __shared__ char smem[];
    const uint32_t sbase = smem_u32(smem);

    const int tid  = threadIdx.x;
    const int wid  = tid >> 5;
    const int lane = tid & 31;
    const int gid  = lane >> 2;
    const int tig  = lane & 3;
    const int wm   = wid & 3;
    const int wn   = wid >> 2;
    const int m0   = blockIdx.y * 128;
    const int n0   = blockIdx.x * NT;
    const int z    = blockIdx.z;
    const int zb   = z >> 4;
    const int zh   = z & 15;

    const __nv_bfloat16* pAh = Ah + (size_t)zb * asb + (size_t)zh * ash;
    const __nv_bfloat16* pAl = Al + (size_t)zb * asb + (size_t)zh * ash;
    const __nv_bfloat16* pWh = Wh + (size_t)zb * wsb + (size_t)zh * wsh;
    const __nv_bfloat16* pWl = Wl + (size_t)zb * wsb + (size_t)zh * wsh;

    const int a_r = lane & 15;
    const int a_c = (lane >> 4) << 3;
    const int w_r = (lane & 7) + ((lane & 16) >> 1);
    const int w_c = ((lane >> 3) & 1) << 3;

    float acc[2][NATOMS][4];
#pragma unroll
    for (int i = 0; i < 2; i++)
#pragma unroll
        for (int j = 0; j < NATOMS; j++)
#pragma unroll
            for (int c = 0; c < 4; c++) acc[i][j][c] = 0.f;

    const int nk = K >> 5;

    auto load_stage = [&](int s, int k0) {
        uint32_t st = sbase + s * STAGE;
#pragma unroll
        for (int i = 0; i < 2; i++) {
            int idx = tid + i * 256;
            int row = idx >> 2;
            int kq  = idx & 3;
            uint32_t doff = (row * SMM_STRIDE + kq * 8) * 2;
            cp16(st + doff,           pAh + (size_t)(m0 + row) * lda + k0 + kq * 8);
            cp16(st + A_BYTES + doff, pAl + (size_t)(m0 + row) * lda + k0 + kq * 8);
        }
#pragma unroll
        for (int i = 0; i < (NT == 128 ? 2 : 1); i++) {
            int idx = tid + i * 256;
            int row = idx >> 2;
            int kq  = idx & 3;
            uint32_t doff = (row * SMM_STRIDE + kq * 8) * 2;
            cp16(st + 2 * A_BYTES + doff,           pWh + (size_t)(n0 + row) * ldw + k0 + kq * 8);
            cp16(st + 2 * A_BYTES + W_BYTES + doff, pWl + (size_t)(n0 + row) * ldw + k0 + kq * 8);
        }
    };

    load_stage(0, 0);
    cp_commit();

    for (int c0 = 0; c0 < nk; c0++) {
        if (c0 + 1 < nk) { load_stage((c0 + 1) & 1, (c0 + 1) * 32); cp_commit(); cp_wait<1>(); }
        else             { cp_wait<0>(); }
        __syncthreads();

        uint32_t st  = sbase + (c0 & 1) * STAGE;
        uint32_t sAh = st;
        uint32_t sAl = st + A_BYTES;
        uint32_t sWh = st + 2 * A_BYTES;
        uint32_t sWl = st + 2 * A_BYTES + W_BYTES;

#pragma unroll
        for (int ks = 0; ks < 2; ks++) {
            const int cb = ks * 16;
            uint32_t afh[2][4], afl[2][4], wf[NATOMS][2];

#pragma unroll
            for (int i = 0; i < 2; i++) {
                int r = wm * 32 + i * 16 + a_r;
                ldsm_x4(afh[i], sAh + (r * SMM_STRIDE + cb + a_c) * 2);
            }
#pragma unroll
            for (int jp = 0; jp < NATOMS / 2; jp++) {
                int n = wn * (NT / 2) + jp * 16 + w_r;
                ldsm_x4(&wf[2 * jp][0], sWh + (n * SMM_STRIDE + cb + w_c) * 2);
            }
#pragma unroll
            for (int i = 0; i < 2; i++)
#pragma unroll
                for (int j = 0; j < NATOMS; j++) mma16816(acc[i][j], afh[i], wf[j]);

#pragma unroll
            for (int i = 0; i < 2; i++) {
                int r = wm * 32 + i * 16 + a_r;
                ldsm_x4(afl[i], sAl + (r * SMM_STRIDE + cb + a_c) * 2);
            }
#pragma unroll
            for (int i = 0; i < 2; i++)
#pragma unroll
                for (int j = 0; j < NATOMS; j++) mma16816(acc[i][j], afl[i], wf[j]);

#pragma unroll
            for (int jp = 0; jp < NATOMS / 2; jp++) {
                int n = wn * (NT / 2) + jp * 16 + w_r;
                ldsm_x4(&wf[2 * jp][0], sWl + (n * SMM_STRIDE + cb + w_c) * 2);
            }
#pragma unroll
            for (int i = 0; i < 2; i++)
#pragma unroll
                for (int j = 0; j < NATOMS; j++) mma16816(acc[i][j], afh[i], wf[j]);
        }
        __syncthreads();
    }

#pragma unroll
    for (int i = 0; i < 2; i++) {
        int row = m0 + wm * 32 + i * 16 + gid;
#pragma unroll
        for (int j = 0; j < NATOMS; j++) {
            int col = n0 + wn * (NT / 2) + j * 8 + tig * 2;
            float b0 = bias ? bias[col] : 0.f;
            float b1 = bias ? bias[col + 1] : 0.f;
            float f0 = acc[i][j][0] * scale + b0;
            float f1 = acc[i][j][1] * scale + b1;
            float f2 = acc[i][j][2] * scale + b0;
            float f3 = acc[i][j][3] * scale + b1;
            if (SPLIT_OUT) {
                uint16_t* pH = (uint16_t*)Ch + (size_t)zb * csb + (size_t)zh * csh;
                uint16_t* pL = (uint16_t*)Cl + (size_t)zb * csb + (size_t)zh * csh;
                __nv_bfloat16 h0 = __float2bfloat16(f0), h1 = __float2bfloat16(f1);
                __nv_bfloat16 h2 = __float2bfloat16(f2), h3 = __float2bfloat16(f3);
                ushort2 H0 = {__bfloat16_as_ushort(h0), __bfloat16_as_ushort(h1)};
                ushort2 H1 = {__bfloat16_as_ushort(h2), __bfloat16_as_ushort(h3)};
                ushort2 L0 = {__bfloat16_as_ushort(__float2bfloat16(f0 - __bfloat162float(h0))),
                              __bfloat16_as_ushort(__float2bfloat16(f1 - __bfloat162float(h1)))};
                ushort2 L1 = {__bfloat16_as_ushort(__float2bfloat16(f2 - __bfloat162float(h2))),
                              __bfloat16_as_ushort(__float2bfloat16(f3 - __bfloat162float(h3)))};
                *(ushort2*)(pH + (size_t)row * ldc + col) = H0;
                *(ushort2*)(pH + (size_t)(row + 8) * ldc + col) = H1;
                *(ushort2*)(pL + (size_t)row * ldc + col) = L0;
                *(ushort2*)(pL + (size_t)(row + 8) * ldc + col) = L1;
            } else {
                float* pC = C + (size_t)zb * csb + (size_t)zh * csh;
                *(float2*)(pC + (size_t)row * ldc + col) = make_float2(f0, f1);
                *(float2*)(pC + (size_t)(row + 8) * ldc + col) = make_float2(f2, f3);
            }
        }
    }
}

// ===========================================================================
// Fused scores + softmax + batch-sum kernel.
// Block = (16 q rows, one head). Per batch: full 16x1024 score tile in
// registers (bf16x3 mma, one pass), row softmax, accumulate into smem
// attacc over 4 batches, emit att as bf16 hi/lo.
// ===========================================================================
constexpr int SS_ATT   = 0;                       // float[16][1032]
constexpr int SS_KH    = 66048;                   // uint16[128*72]
constexpr int SS_KL    = SS_KH + 18432;
constexpr int SS_QH    = SS_KL + 18432;           // uint16[16*72]
constexpr int SS_QL    = SS_QH + 2304;
constexpr int SS_RED   = SS_QL + 2304;            // float[8][16]
constexpr int SS_MROW  = SS_RED + 512;            // float[16]
constexpr int SS_INVZ  = SS_MROW + 64;            // float[16]
constexpr int SS_TOTAL = SS_INVZ + 64 + 128;      // ~108.4KB

__global__ __launch_bounds__(256, 2) void score_softmax_kernel(
    const __nv_bfloat16* __restrict__ qh, const __nv_bfloat16* __restrict__ ql,
    const __nv_bfloat16* __restrict__ kh, const __nv_bfloat16* __restrict__ kl,
    const float* __restrict__ mask, const int* __restrict__ flag,
    __nv_bfloat16* __restrict__ atth, __nv_bfloat16* __restrict__ attl)
{
    extern __shared__ char smem[];
    const uint32_t sbase = smem_u32(smem);
    float*    attacc = (float*)(smem + SS_ATT);      // stride 1032
    float*    red    = (float*)(smem + SS_RED);
    float*    mrow   = (float*)(smem + SS_MROW);
    float*    invz   = (float*)(smem + SS_INVZ);

    const int tid  = threadIdx.x;
    const int wj   = tid >> 5;
    const int lane = tid & 31;
    const int gid  = lane >> 2;
    const int tig  = lane & 3;
    const int q0   = blockIdx.x * 16;
    const int h    = blockIdx.y;
    const int maskflag = *flag;

    const int a_r = lane & 15;
    const int a_c = (lane >> 4) << 3;
    const int w_r = (lane & 7) + ((lane & 16) >> 1);
    const int w_c = ((lane >> 3) & 1) << 3;

    // zero attacc (incl. padding)
    for (int i = tid; i < 16 * 1032; i += 256) attacc[i] = 0.f;

    float sc[8][2][4];

    for (int b = 0; b < NB; b++) {
        // ---- load q tile (16 rows x 64 hw, stride 72) ----
        {
            int row = tid >> 4;
            int c4  = (tid & 15) * 4;
            size_t src = (size_t)(b * SEQ + q0 + row) * DM + h * HDIM + c4;
            *(ushort4*)(smem + SS_QH + (row * 72 + c4) * 2) =
                *(const ushort4*)((const uint16_t*)qh + src);
            *(ushort4*)(smem + SS_QL + (row * 72 + c4) * 2) =
                *(const ushort4*)((const uint16_t*)ql + src);
        }
        __syncthreads();   // q ready; also protects attacc zero / prior stats

#pragma unroll
        for (int jc2 = 0; jc2 < 8; jc2++)
#pragma unroll
            for (int a = 0; a < 2; a++)
#pragma unroll
                for (int c = 0; c < 4; c++) sc[jc2][a][c] = 0.f;

        for (int jc = 0; jc < 8; jc++) {
            // ---- load k chunk (128 rows x 64 hw) ----
#pragma unroll
            for (int r2 = 0; r2 < 8; r2++) {
                int idx = tid + r2 * 256;
                int row = idx >> 4;
                int c4  = (idx & 15) * 4;
                size_t src = (size_t)(b * SEQ + jc * 128 + row) * DM + h * HDIM + c4;
                *(ushort4*)(smem + SS_KH + (row * 72 + c4) * 2) =
                    *(const ushort4*)((const uint16_t*)kh + src);
                *(ushort4*)(smem + SS_KL + (row * 72 + c4) * 2) =
                    *(const ushort4*)((const uint16_t*)kl + src);
            }
            __syncthreads();

#pragma unroll
            for (int ka = 0; ka < 4; ka++) {
                uint32_t afh[4], afl[4], wfh[4], wfl[4];
                uint32_t qoff = (a_r * 72 + ka * 16 + a_c) * 2;
                ldsm_x4(afh, sbase + SS_QH + qoff);
                ldsm_x4(afl, sbase + SS_QL + qoff);
                uint32_t koff = ((wj * 16 + w_r) * 72 + ka * 16 + w_c) * 2;
                ldsm_x4(wfh, sbase + SS_KH + koff);
                ldsm_x4(wfl, sbase + SS_KL + koff);
                mma16816(sc[jc][0], afh, wfh + 0);
                mma16816(sc[jc][1], afh, wfh + 2);
                mma16816(sc[jc][0], afl, wfh + 0);
                mma16816(sc[jc][1], afl, wfh + 2);
                mma16816(sc[jc][0], afh, wfl + 0);
                mma16816(sc[jc][1], afh, wfl + 2);
            }
            __syncthreads();   // before next chunk overwrites k
        }

        // ---- scale + optional mask ----
#pragma unroll
        for (int jc = 0; jc < 8; jc++)
#pragma unroll
            for (int a = 0; a < 2; a++)
#pragma unroll
                for (int c = 0; c < 4; c++) sc[jc][a][c] *= 0.125f;

        if (maskflag) {
#pragma unroll
            for (int jc = 0; jc < 8; jc++)
#pragma unroll
                for (int a = 0; a < 2; a++)
#pragma unroll
                    for (int c = 0; c < 4; c++) {
                        int r   = gid + ((c >> 1) << 3);
                        int col = jc * 128 + wj * 16 + a * 8 + tig * 2 + (c & 1);
                        sc[jc][a][c] += mask[(size_t)(q0 + r) * SEQ + col];
                    }
        }

        // ---- row max ----
        float mx0 = -INFINITY, mx1 = -INFINITY;
#pragma unroll
        for (int jc = 0; jc < 8; jc++)
#pragma unroll
            for (int a = 0; a < 2; a++) {
                mx0 = fmaxf(mx0, fmaxf(sc[jc][a][0], sc[jc][a][1]));
                mx1 = fmaxf(mx1, fmaxf(sc[jc][a][2], sc[jc][a][3]));
            }
        mx0 = fmaxf(mx0, __shfl_xor_sync(0xffffffffu, mx0, 1));
        mx0 = fmaxf(mx0, __shfl_xor_sync(0xffffffffu, mx0, 2));
        mx1 = fmaxf(mx1, __shfl_xor_sync(0xffffffffu, mx1, 1));
        mx1 = fmaxf(mx1, __shfl_xor_sync(0xffffffffu, mx1, 2));
        if (tig == 0) { red[wj * 16 + gid] = mx0; red[wj * 16 + gid + 8] = mx1; }
        __syncthreads();
        if (tid < 16) {
            float m = red[tid];
#pragma unroll
            for (int w = 1; w < 8; w++) m = fmaxf(m, red[w * 16 + tid]);
            mrow[tid] = m;
        }
        __syncthreads();

        // ---- row Z ----
        float m0 = mrow[gid], m1 = mrow[gid + 8];
        float z0 = 0.f, z1 = 0.f;
#pragma unroll
        for (int jc = 0; jc < 8; jc++)
#pragma unroll
            for (int a = 0; a < 2; a++) {
                z0 += __expf(sc[jc][a][0] - m0) + __expf(sc[jc][a][1] - m0);
                z1 += __expf(sc[jc][a][2] - m1) + __expf(sc[jc][a][3] - m1);
            }
        z0 += __shfl_xor_sync(0xffffffffu, z0, 1);
        z0 += __shfl_xor_sync(0xffffffffu, z0, 2);
        z1 += __shfl_xor_sync(0xffffffffu, z1, 1);
        z1 += __shfl_xor_sync(0xffffffffu, z1, 2);
        if (tig == 0) { red[wj * 16 + gid] = z0; red[wj * 16 + gid + 8] = z1; }
        __syncthreads();
        if (tid < 16) {
            float z = 0.f;
#pragma unroll
            for (int w = 0; w < 8; w++) z += red[w * 16 + tid];
            invz[tid] = (z > 0.f && isfinite(z)) ? (1.f / z) : 0.f;
        }
        __syncthreads();

        // ---- accumulate p into attacc (each element owned by one thread) ----
        float iz0 = invz[gid], iz1 = invz[gid + 8];
#pragma unroll
        for (int jc = 0; jc < 8; jc++)
#pragma unroll
            for (int a = 0; a < 2; a++) {
                int colb = jc * 128 + wj * 16 + a * 8 + tig * 2;
                if (iz0 != 0.f) {
                    attacc[gid * 1032 + colb]     += __expf(sc[jc][a][0] - m0) * iz0;
                    attacc[gid * 1032 + colb + 1] += __expf(sc[jc][a][1] - m0) * iz0;
                }
                if (iz1 != 0.f) {
                    attacc[(gid + 8) * 1032 + colb]     += __expf(sc[jc][a][2] - m1) * iz1;
                    attacc[(gid + 8) * 1032 + colb + 1] += __expf(sc[jc][a][3] - m1) * iz1;
                }
            }
        __syncthreads();
    }

    // ---- emit att as bf16 hi/lo ----
#pragma unroll
    for (int i = 0; i < 32; i++) {
        int idx  = tid + i * 256;          // pairs: 16*512 = 8192 float2
        int row  = idx >> 9;
        int col2 = (idx & 511) * 2;
        float2 f = *(float2*)&attacc[row * 1032 + col2];
        __nv_bfloat16 h0 = __float2bfloat16(f.x);
        __nv_bfloat16 h1 = __float2bfloat16(f.y);
        ushort2 H = {__bfloat16_as_ushort(h0), __bfloat16_as_ushort(h1)};
        ushort2 L = {__bfloat16_as_ushort(__float2bfloat16(f.x - __bfloat162float(h0))),
                     __bfloat16_as_ushort(__float2bfloat16(f.y - __bfloat162float(h1)))};
        size_t off = ((size_t)h * SEQ + q0 + row) * SEQ + col2;
        *(ushort2*)((uint16_t*)atth + off) = H;
        *(ushort2*)((uint16_t*)attl + off) = L;
    }
}

// ===========================================================================
extern "C" void kernel_launch(void* const* d_in, const int* in_sizes, int n_in,
                              void* d_out, int out_size)
{
    const float* x    = (const float*)d_in[0];
    const float* y    = (const float*)d_in[1];
    const float* mask = (const float*)d_in[2];
    const float* Wq   = (const float*)d_in[3];
    const float* bq   = (const float*)d_in[4];
    const float* Wk   = (const float*)d_in[5];
    const float* bk   = (const float*)d_in[6];
    const float* Wv   = (const float*)d_in[7];
    const float* bv   = (const float*)d_in[8];
    const float* Wo   = (const float*)d_in[9];
    const float* bo   = (const float*)d_in[10];
    float* out = (float*)d_out;

    int* flag;
    cudaGetSymbolAddress((void**)&flag, g_maskflag);

    __nv_bfloat16 *yh, *yl, *xh, *xl, *qh, *ql, *kh, *kl, *vh, *vl;
    __nv_bfloat16 *vth, *vtl, *avh, *avl, *atth, *attl;
    __nv_bfloat16 *wqh, *wql, *wkh, *wkl, *wvh, *wvl, *woh, *wol;
    cudaGetSymbolAddress((void**)&yh, g_yh);   cudaGetSymbolAddress((void**)&yl, g_yl);
    cudaGetSymbolAddress((void**)&xh, g_xh);   cudaGetSymbolAddress((void**)&xl, g_xl);
    cudaGetSymbolAddress((void**)&qh, g_qh);   cudaGetSymbolAddress((void**)&ql, g_ql);
    cudaGetSymbolAddress((void**)&kh, g_kh);   cudaGetSymbolAddress((void**)&kl, g_kl);
    cudaGetSymbolAddress((void**)&vh, g_vh);   cudaGetSymbolAddress((void**)&vl, g_vl);
    cudaGetSymbolAddress((void**)&vth, g_vth); cudaGetSymbolAddress((void**)&vtl, g_vtl);
    cudaGetSymbolAddress((void**)&avh, g_avh); cudaGetSymbolAddress((void**)&avl, g_avl);
    cudaGetSymbolAddress((void**)&atth, g_atth); cudaGetSymbolAddress((void**)&attl, g_attl);
    cudaGetSymbolAddress((void**)&wqh, g_wqh); cudaGetSymbolAddress((void**)&wql, g_wql);
    cudaGetSymbolAddress((void**)&wkh, g_wkh); cudaGetSymbolAddress((void**)&wkl, g_wkl);
    cudaGetSymbolAddress((void**)&wvh, g_wvh); cudaGetSymbolAddress((void**)&wvl, g_wvl);
    cudaGetSymbolAddress((void**)&woh, g_woh); cudaGetSymbolAddress((void**)&wol, g_wol);

    constexpr int SMEM128 = 2 * (2 * 128 * SMM_STRIDE * 2 + 2 * 128 * SMM_STRIDE * 2); // 81920
    constexpr int SMEM64  = 2 * (2 * 128 * SMM_STRIDE * 2 + 2 * 64 * SMM_STRIDE * 2);  // 61440
    cudaFuncSetAttribute(mm3_kernel<128, true>,  cudaFuncAttributeMaxDynamicSharedMemorySize, SMEM128);
    cudaFuncSetAttribute(mm3_kernel<128, false>, cudaFuncAttributeMaxDynamicSharedMemorySize, SMEM128);
    cudaFuncSetAttribute(mm3_kernel<64, true>,   cudaFuncAttributeMaxDynamicSharedMemorySize, SMEM64);
    cudaFuncSetAttribute(score_softmax_kernel,   cudaFuncAttributeMaxDynamicSharedMemorySize, SS_TOTAL);

    const size_t SDM = (size_t)SEQ * DM;
    const size_t SS  = (size_t)SEQ * SEQ;

    // ---- input splits (1 launch) + flag zero ----
    split6_kernel<<<dim3(MR * DM / 4 / 256, 6), 256>>>(
        y, yh, yl, x, xh, xl,
        Wq, wqh, wql, Wk, wkh, wkl, Wv, wvh, wvl, Wo, woh, wol, flag);

    // ---- mask nonzero flag ----
    maskchk_kernel<<<SEQ * SEQ / 4 / 256, 256>>>(mask, flag);

    // ---- projections: split bf16 outputs directly ----
    dim3 pgrid(DM / 128, MR / 128, 1);
    mm3_kernel<128, true><<<pgrid, 256, SMEM128>>>(
        yh, yl, 0, 0, DM, wqh, wql, 0, 0, DM,
        bq, nullptr, qh, ql, 0, 0, DM, DM, 1.f);
    mm3_kernel<128, true><<<pgrid, 256, SMEM128>>>(
        xh, xl, 0, 0, DM, wkh, wkl, 0, 0, DM,
        bk, nullptr, kh, kl, 0, 0, DM, DM, 1.f);
    mm3_kernel<128, true><<<pgrid, 256, SMEM128>>>(
        xh, xl, 0, 0, DM, wvh, wvl, 0, 0, DM,
        bv, nullptr, vh, vl, 0, 0, DM, DM, 1.f);

    // ---- v transpose (bf16) ----
    transpose_v_kernel<<<dim3(SEQ / 64, NB * NHEAD), 256>>>(vh, vl, vth, vtl);

    // ---- fused scores + softmax + batch-sum -> bf16 hi/lo att ----
    score_softmax_kernel<<<dim3(SEQ / 16, NHEAD), 256, SS_TOTAL>>>(
        qh, ql, kh, kl, mask, flag, atth, attl);

    // ---- AV: av[b,:,h*64+d] = att_h @ vt_bh^T  (N=64, K=1024), split out ----
    mm3_kernel<64, true><<<dim3(1, SEQ / 128, NB * NHEAD), 256, SMEM64>>>(
        atth, attl, 0, SS, SEQ,
        vth, vtl, (size_t)NHEAD * HDIM * SEQ, (size_t)HDIM * SEQ, SEQ,
        nullptr, nullptr, avh, avl, SDM, (size_t)HDIM, DM, SEQ, 1.f);

    // ---- output projection (fp32 out + bias) ----
    mm3_kernel<128, false><<<pgrid, 256, SMEM128>>>(
        avh, avl, 0, 0, DM, woh, wol, 0, 0, DM,
        bo, out, nullptr, nullptr, 0, 0, DM, DM, 1.f);
}

// round 15
// speedup vs baseline: 1.2222x; 1.2222x over previous
#include <cuda_runtime.h>
#include <cuda_bf16.h>
#include <math.h>
#include <stdint.h>

// Problem constants
constexpr int SEQ   = 1024;
constexpr int DM    = 1024;
constexpr int NHEAD = 16;
constexpr int HDIM  = 64;
constexpr int NB    = 4;
constexpr int MR    = NB * SEQ;

constexpr size_t ACT = (size_t)MR * DM;   // one activation slice
constexpr size_t WSZ = (size_t)DM * DM;   // one weight slice

// ---------------- scratch (device globals; no allocation allowed) ----------
__device__ float g_s [(size_t)NB * NHEAD * SEQ * SEQ];   // raw scores (b,h,q,j)
__device__ float g_bqkv[3 * DM];                          // bq|bk|bv

__device__ __nv_bfloat16 g_acth[3 * ACT];   // y | x | x  (hi)
__device__ __nv_bfloat16 g_actl[3 * ACT];
__device__ __nv_bfloat16 g_wh3[3 * WSZ];    // wq | wk | wv (hi)
__device__ __nv_bfloat16 g_wl3[3 * WSZ];
__device__ __nv_bfloat16 g_qkvh[3 * ACT];   // q | k | v (hi)
__device__ __nv_bfloat16 g_qkvl[3 * ACT];
__device__ __nv_bfloat16 g_vth[(size_t)MR * DM];   // v^T per (b,h): [b][h][d][j]
__device__ __nv_bfloat16 g_vtl[(size_t)MR * DM];
__device__ __nv_bfloat16 g_avh[(size_t)MR * DM];
__device__ __nv_bfloat16 g_avl[(size_t)MR * DM];
__device__ __nv_bfloat16 g_atth[(size_t)NHEAD * SEQ * SEQ];
__device__ __nv_bfloat16 g_attl[(size_t)NHEAD * SEQ * SEQ];
__device__ __nv_bfloat16 g_woh[WSZ];
__device__ __nv_bfloat16 g_wol[WSZ];

// ===========================================================================
// helpers
// ===========================================================================
__device__ __forceinline__ uint32_t smem_u32(const void* p) {
    uint32_t r;
    asm("{ .reg .u64 t; cvta.to.shared.u64 t, %1; cvt.u32.u64 %0, t; }"
        : "=r"(r) : "l"(p));
    return r;
}
__device__ __forceinline__ void cp16(uint32_t dst, const void* src) {
    asm volatile("cp.async.cg.shared.global [%0], [%1], 16;" :: "r"(dst), "l"(src));
}
__device__ __forceinline__ void cp_commit() {
    asm volatile("cp.async.commit_group;" ::: "memory");
}
template <int N>
__device__ __forceinline__ void cp_wait() {
    asm volatile("cp.async.wait_group %0;" :: "n"(N) : "memory");
}
__device__ __forceinline__ void ldsm_x4(uint32_t* r, uint32_t addr) {
    asm volatile("ldmatrix.sync.aligned.m8n8.x4.shared.b16 {%0,%1,%2,%3}, [%4];"
        : "=r"(r[0]), "=r"(r[1]), "=r"(r[2]), "=r"(r[3]) : "r"(addr));
}
__device__ __forceinline__ void mma16816(
    float* d, const uint32_t* a, const uint32_t* b)
{
    asm volatile(
        "mma.sync.aligned.m16n8k16.row.col.f32.bf16.bf16.f32 "
        "{%0,%1,%2,%3}, {%4,%5,%6,%7}, {%8,%9}, {%0,%1,%2,%3};"
        : "+f"(d[0]), "+f"(d[1]), "+f"(d[2]), "+f"(d[3])
        : "r"(a[0]), "r"(a[1]), "r"(a[2]), "r"(a[3]), "r"(b[0]), "r"(b[1]));
}

// ===========================================================================
// input splits into sliced buffers (1 launch, grid.y = 8 segments)
// segs 0..2: y,x,x -> acth/actl slices; 3..5: wq,wk,wv -> wh3/wl3;
// seg 6: wo -> woh/wol; seg 7: bias copy bq|bk|bv -> g_bqkv.
// ===========================================================================
__global__ __launch_bounds__(256) void split8_kernel(
    const float* __restrict__ y,  const float* __restrict__ x,
    const float* __restrict__ wq, const float* __restrict__ wk,
    const float* __restrict__ wv, const float* __restrict__ wo,
    const float* __restrict__ bq, const float* __restrict__ bk,
    const float* __restrict__ bv,
    __nv_bfloat16* acth, __nv_bfloat16* actl,
    __nv_bfloat16* wh3,  __nv_bfloat16* wl3,
    __nv_bfloat16* woh,  __nv_bfloat16* wol,
    float* bqkv)
{
    const int seg = blockIdx.y;
    const int tid = threadIdx.x;

    if (seg == 7) {
        if (blockIdx.x == 0 && tid < 256) {
            ((float4*)bqkv)[tid]       = ((const float4*)bq)[tid];
            ((float4*)bqkv)[tid + 256] = ((const float4*)bk)[tid];
            ((float4*)bqkv)[tid + 512] = ((const float4*)bv)[tid];
        }
        return;
    }

    const float* in; __nv_bfloat16 *hi, *lo; int n4;
    if (seg < 3) {
        in = (seg == 0) ? y : x;
        hi = acth + (size_t)seg * ACT;
        lo = actl + (size_t)seg * ACT;
        n4 = (int)(ACT / 4);
    } else if (seg < 6) {
        in = (seg == 3) ? wq : (seg == 4) ? wk : wv;
        hi = wh3 + (size_t)(seg - 3) * WSZ;
        lo = wl3 + (size_t)(seg - 3) * WSZ;
        n4 = (int)(WSZ / 4);
    } else {
        in = wo; hi = woh; lo = wol; n4 = (int)(WSZ / 4);
    }

    int i = blockIdx.x * blockDim.x + tid;
    if (i >= n4) return;
    float4 v = ((const float4*)in)[i];
    __nv_bfloat16 h0 = __float2bfloat16(v.x);
    __nv_bfloat16 h1 = __float2bfloat16(v.y);
    __nv_bfloat16 h2 = __float2bfloat16(v.z);
    __nv_bfloat16 h3 = __float2bfloat16(v.w);
    ushort4 H, L;
    H.x = __bfloat16_as_ushort(h0); H.y = __bfloat16_as_ushort(h1);
    H.z = __bfloat16_as_ushort(h2); H.w = __bfloat16_as_ushort(h3);
    L.x = __bfloat16_as_ushort(__float2bfloat16(v.x - __bfloat162float(h0)));
    L.y = __bfloat16_as_ushort(__float2bfloat16(v.y - __bfloat162float(h1)));
    L.z = __bfloat16_as_ushort(__float2bfloat16(v.z - __bfloat162float(h2)));
    L.w = __bfloat16_as_ushort(__float2bfloat16(v.w - __bfloat162float(h3)));
    ((ushort4*)hi)[i] = H;
    ((ushort4*)lo)[i] = L;
}

// ===========================================================================
// bf16 transpose of v hi/lo:  vt[b][h][d][j] = v[b*S+j][h*64+d]
// ===========================================================================
__global__ __launch_bounds__(256) void transpose_v_kernel(
    const __nv_bfloat16* __restrict__ vh, const __nv_bfloat16* __restrict__ vl,
    __nv_bfloat16* __restrict__ vth, __nv_bfloat16* __restrict__ vtl)
{
    __shared__ uint16_t th[64][72];
    __shared__ uint16_t tl[64][72];
    const int bh = blockIdx.y;
    const int b  = bh >> 4;
    const int h  = bh & 15;
    const int j0 = blockIdx.x * 64;
    const int tid = threadIdx.x;

#pragma unroll
    for (int i = 0; i < 4; i++) {
        int idx = tid + i * 256;
        int j   = idx >> 4;
        int dq  = (idx & 15) * 4;
        size_t off = (size_t)(b * SEQ + j0 + j) * DM + h * HDIM + dq;
        ushort4 a = *(const ushort4*)((const uint16_t*)vh + off);
        ushort4 c = *(const ushort4*)((const uint16_t*)vl + off);
        th[dq + 0][j] = a.x; th[dq + 1][j] = a.y; th[dq + 2][j] = a.z; th[dq + 3][j] = a.w;
        tl[dq + 0][j] = c.x; tl[dq + 1][j] = c.y; tl[dq + 2][j] = c.z; tl[dq + 3][j] = c.w;
    }
    __syncthreads();

    const int d  = tid >> 2;
    const int jq = (tid & 3) * 16;
    uint16_t* oh = (uint16_t*)vth + ((size_t)bh * HDIM + d) * SEQ + j0 + jq;
    uint16_t* ol = (uint16_t*)vtl + ((size_t)bh * HDIM + d) * SEQ + j0 + jq;
#pragma unroll
    for (int c = 0; c < 4; c++) {
        ushort4 A, B;
        A.x = th[d][jq + c * 4 + 0]; A.y = th[d][jq + c * 4 + 1];
        A.z = th[d][jq + c * 4 + 2]; A.w = th[d][jq + c * 4 + 3];
        B.x = tl[d][jq + c * 4 + 0]; B.y = tl[d][jq + c * 4 + 1];
        B.z = tl[d][jq + c * 4 + 2]; B.w = tl[d][jq + c * 4 + 3];
        *(ushort4*)(oh + c * 4) = A;
        *(ushort4*)(ol + c * 4) = B;
    }
}

// ===========================================================================
// Generic bf16x3 compensated GEMM, ldmatrix fragments, cp.async 2-stage,
// SINGLE-sync mainloop (cp_wait -> sync -> issue next loads -> compute).
// bias indexed as bias[zh*bsh + col].
// ===========================================================================
#define SMM_STRIDE 40   // 32 k elems + 8 pad (bf16)

template <int NT, bool SPLIT_OUT>
__global__ __launch_bounds__(256, 2) void mm3_kernel(
    const __nv_bfloat16* __restrict__ Ah, const __nv_bfloat16* __restrict__ Al,
    size_t asb, size_t ash, int lda,
    const __nv_bfloat16* __restrict__ Wh, const __nv_bfloat16* __restrict__ Wl,
    size_t wsb, size_t wsh, int ldw,
    const float* __restrict__ bias, int bsh,
    float* __restrict__ C, __nv_bfloat16* __restrict__ Ch, __nv_bfloat16* __restrict__ Cl,
    size_t csb, size_t csh, int ldc,
    int K, float scale)
{
    constexpr int NATOMS  = NT / 16;
    constexpr int A_BYTES = 128 * SMM_STRIDE * 2;
    constexpr int W_BYTES = NT * SMM_STRIDE * 2;
    constexpr int STAGE   = 2 * A_BYTES + 2 * W_BYTES;

    extern __shared__ char smem[];
    const uint32_t sbase = smem_u32(smem);

    const int tid  = threadIdx.x;
    const int wid  = tid >> 5;
    const int lane = tid & 31;
    const int gid  = lane >> 2;
    const int tig  = lane & 3;
    const int wm   = wid & 3;
    const int wn   = wid >> 2;
    const int m0   = blockIdx.y * 128;
    const int n0   = blockIdx.x * NT;
    const int z    = blockIdx.z;
    const int zb   = z >> 4;
    const int zh   = z & 15;

    const __nv_bfloat16* pAh = Ah + (size_t)zb * asb + (size_t)zh * ash;
    const __nv_bfloat16* pAl = Al + (size_t)zb * asb + (size_t)zh * ash;
    const __nv_bfloat16* pWh = Wh + (size_t)zb * wsb + (size_t)zh * wsh;
    const __nv_bfloat16* pWl = Wl + (size_t)zb * wsb + (size_t)zh * wsh;

    const int a_r = lane & 15;
    const int a_c = (lane >> 4) << 3;
    const int w_r = (lane & 7) + ((lane & 16) >> 1);
    const int w_c = ((lane >> 3) & 1) << 3;

    float acc[2][NATOMS][4];
#pragma unroll
    for (int i = 0; i < 2; i++)
#pragma unroll
        for (int j = 0; j < NATOMS; j++)
#pragma unroll
            for (int c = 0; c < 4; c++) acc[i][j][c] = 0.f;

    const int nk = K >> 5;

    auto load_stage = [&](int s, int k0) {
        uint32_t st = sbase + s * STAGE;
#pragma unroll
        for (int i = 0; i < 2; i++) {
            int idx = tid + i * 256;
            int row = idx >> 2;
            int kq  = idx & 3;
            uint32_t doff = (row * SMM_STRIDE + kq * 8) * 2;
            cp16(st + doff,           pAh + (size_t)(m0 + row) * lda + k0 + kq * 8);
            cp16(st + A_BYTES + doff, pAl + (size_t)(m0 + row) * lda + k0 + kq * 8);
        }
#pragma unroll
        for (int i = 0; i < (NT == 128 ? 2 : 1); i++) {
            int idx = tid + i * 256;
            int row = idx >> 2;
            int kq  = idx & 3;
            uint32_t doff = (row * SMM_STRIDE + kq * 8) * 2;
            cp16(st + 2 * A_BYTES + doff,           pWh + (size_t)(n0 + row) * ldw + k0 + kq * 8);
            cp16(st + 2 * A_BYTES + W_BYTES + doff, pWl + (size_t)(n0 + row) * ldw + k0 + kq * 8);
        }
    };

    load_stage(0, 0);
    cp_commit();

    for (int c0 = 0; c0 < nk; c0++) {
        // wait for this stage's data; barrier doubles as "previous compute
        // drained" so the loads below can safely overwrite the other buffer.
        cp_wait<0>();
        __syncthreads();
        if (c0 + 1 < nk) { load_stage((c0 + 1) & 1, (c0 + 1) * 32); cp_commit(); }

        uint32_t st  = sbase + (c0 & 1) * STAGE;
        uint32_t sAh = st;
        uint32_t sAl = st + A_BYTES;
        uint32_t sWh = st + 2 * A_BYTES;
        uint32_t sWl = st + 2 * A_BYTES + W_BYTES;

#pragma unroll
        for (int ks = 0; ks < 2; ks++) {
            const int cb = ks * 16;
            uint32_t afh[2][4], afl[2][4], wf[NATOMS][2];

#pragma unroll
            for (int i = 0; i < 2; i++) {
                int r = wm * 32 + i * 16 + a_r;
                ldsm_x4(afh[i], sAh + (r * SMM_STRIDE + cb + a_c) * 2);
            }
#pragma unroll
            for (int jp = 0; jp < NATOMS / 2; jp++) {
                int n = wn * (NT / 2) + jp * 16 + w_r;
                ldsm_x4(&wf[2 * jp][0], sWh + (n * SMM_STRIDE + cb + w_c) * 2);
            }
#pragma unroll
            for (int i = 0; i < 2; i++)
#pragma unroll
                for (int j = 0; j < NATOMS; j++) mma16816(acc[i][j], afh[i], wf[j]);

#pragma unroll
            for (int i = 0; i < 2; i++) {
                int r = wm * 32 + i * 16 + a_r;
                ldsm_x4(afl[i], sAl + (r * SMM_STRIDE + cb + a_c) * 2);
            }
#pragma unroll
            for (int i = 0; i < 2; i++)
#pragma unroll
                for (int j = 0; j < NATOMS; j++) mma16816(acc[i][j], afl[i], wf[j]);

#pragma unroll
            for (int jp = 0; jp < NATOMS / 2; jp++) {
                int n = wn * (NT / 2) + jp * 16 + w_r;
                ldsm_x4(&wf[2 * jp][0], sWl + (n * SMM_STRIDE + cb + w_c) * 2);
            }
#pragma unroll
            for (int i = 0; i < 2; i++)
#pragma unroll
                for (int j = 0; j < NATOMS; j++) mma16816(acc[i][j], afh[i], wf[j]);
        }
    }

    // ---- epilogue (register-private; no barrier needed) ----
#pragma unroll
    for (int i = 0; i < 2; i++) {
        int row = m0 + wm * 32 + i * 16 + gid;
#pragma unroll
        for (int j = 0; j < NATOMS; j++) {
            int col = n0 + wn * (NT / 2) + j * 8 + tig * 2;
            float b0 = bias ? bias[zh * bsh + col] : 0.f;
            float b1 = bias ? bias[zh * bsh + col + 1] : 0.f;
            float f0 = acc[i][j][0] * scale + b0;
            float f1 = acc[i][j][1] * scale + b1;
            float f2 = acc[i][j][2] * scale + b0;
            float f3 = acc[i][j][3] * scale + b1;
            if (SPLIT_OUT) {
                uint16_t* pH = (uint16_t*)Ch + (size_t)zb * csb + (size_t)zh * csh;
                uint16_t* pL = (uint16_t*)Cl + (size_t)zb * csb + (size_t)zh * csh;
                __nv_bfloat16 h0 = __float2bfloat16(f0), h1 = __float2bfloat16(f1);
                __nv_bfloat16 h2 = __float2bfloat16(f2), h3 = __float2bfloat16(f3);
                ushort2 H0 = {__bfloat16_as_ushort(h0), __bfloat16_as_ushort(h1)};
                ushort2 H1 = {__bfloat16_as_ushort(h2), __bfloat16_as_ushort(h3)};
                ushort2 L0 = {__bfloat16_as_ushort(__float2bfloat16(f0 - __bfloat162float(h0))),
                              __bfloat16_as_ushort(__float2bfloat16(f1 - __bfloat162float(h1)))};
                ushort2 L1 = {__bfloat16_as_ushort(__float2bfloat16(f2 - __bfloat162float(h2))),
                              __bfloat16_as_ushort(__float2bfloat16(f3 - __bfloat162float(h3)))};
                *(ushort2*)(pH + (size_t)row * ldc + col) = H0;
                *(ushort2*)(pH + (size_t)(row + 8) * ldc + col) = H1;
                *(ushort2*)(pL + (size_t)row * ldc + col) = L0;
                *(ushort2*)(pL + (size_t)(row + 8) * ldc + col) = L1;
            } else {
                float* pC = C + (size_t)zb * csb + (size_t)zh * csh;
                *(float2*)(pC + (size_t)row * ldc + col) = make_float2(f0, f1);
                *(float2*)(pC + (size_t)(row + 8) * ldc + col) = make_float2(f2, f3);
            }
        }
    }
}

// ===========================================================================
// Softmax over j (+mask), NaN->0, sum over batch; emits bf16 hi/lo att.
// (unchanged from R11 winner)
// ===========================================================================
__global__ __launch_bounds__(256) void softmax_sum_kernel(
    const float* __restrict__ s, const float* __restrict__ mask,
    __nv_bfloat16* __restrict__ atth, __nv_bfloat16* __restrict__ attl)
{
    __shared__ float red[8];

    const int h   = blockIdx.x >> 10;
    const int qi  = blockIdx.x & 1023;
    const int tid = threadIdx.x;
    const int lane = tid & 31;
    const int warp = tid >> 5;

    float mv[4];
#pragma unroll
    for (int u = 0; u < 4; u++) mv[u] = mask[(size_t)qi * SEQ + tid + u * 256];

    float facc[4] = {0.f, 0.f, 0.f, 0.f};

    for (int b = 0; b < NB; b++) {
        const float* srow = s + (((size_t)(b * NHEAD + h)) * SEQ + qi) * SEQ;
        float rv[4];
        float m = -INFINITY;
#pragma unroll
        for (int u = 0; u < 4; u++) {
            rv[u] = srow[tid + u * 256] + mv[u];
            m = fmaxf(m, rv[u]);
        }
#pragma unroll
        for (int o = 16; o > 0; o >>= 1) m = fmaxf(m, __shfl_xor_sync(0xffffffffu, m, o));
        __syncthreads();
        if (lane == 0) red[warp] = m;
        __syncthreads();
        m = red[0];
#pragma unroll
        for (int w = 1; w < 8; w++) m = fmaxf(m, red[w]);

        float ssum = 0.f;
#pragma unroll
        for (int u = 0; u < 4; u++) {
            rv[u] = __expf(rv[u] - m);
            ssum += rv[u];
        }
#pragma unroll
        for (int o = 16; o > 0; o >>= 1) ssum += __shfl_xor_sync(0xffffffffu, ssum, o);
        __syncthreads();
        if (lane == 0) red[warp] = ssum;
        __syncthreads();
        ssum = 0.f;
#pragma unroll
        for (int w = 0; w < 8; w++) ssum += red[w];

        if (ssum > 0.f && isfinite(ssum)) {
            float inv = 1.f / ssum;
#pragma unroll
            for (int u = 0; u < 4; u++) facc[u] += rv[u] * inv;
        }
    }

    size_t rowoff = ((size_t)h * SEQ + qi) * SEQ;
#pragma unroll
    for (int u = 0; u < 4; u++) {
        float f = facc[u];
        __nv_bfloat16 hi = __float2bfloat16(f);
        atth[rowoff + tid + u * 256] = hi;
        attl[rowoff + tid + u * 256] = __float2bfloat16(f - __bfloat162float(hi));
    }
}

// ===========================================================================
extern "C" void kernel_launch(void* const* d_in, const int* in_sizes, int n_in,
                              void* d_out, int out_size)
{
    const float* x    = (const float*)d_in[0];
    const float* y    = (const float*)d_in[1];
    const float* mask = (const float*)d_in[2];
    const float* Wq   = (const float*)d_in[3];
    const float* bq   = (const float*)d_in[4];
    const float* Wk   = (const float*)d_in[5];
    const float* bk   = (const float*)d_in[6];
    const float* Wv   = (const float*)d_in[7];
    const float* bv   = (const float*)d_in[8];
    const float* Wo   = (const float*)d_in[9];
    const float* bo   = (const float*)d_in[10];
    float* out = (float*)d_out;

    float *sc, *bqkv;
    cudaGetSymbolAddress((void**)&sc,   g_s);
    cudaGetSymbolAddress((void**)&bqkv, g_bqkv);

    __nv_bfloat16 *acth, *actl, *wh3, *wl3, *qkvh, *qkvl;
    __nv_bfloat16 *vth, *vtl, *avh, *avl, *atth, *attl, *woh, *wol;
    cudaGetSymbolAddress((void**)&acth, g_acth); cudaGetSymbolAddress((void**)&actl, g_actl);
    cudaGetSymbolAddress((void**)&wh3, g_wh3);   cudaGetSymbolAddress((void**)&wl3, g_wl3);
    cudaGetSymbolAddress((void**)&qkvh, g_qkvh); cudaGetSymbolAddress((void**)&qkvl, g_qkvl);
    cudaGetSymbolAddress((void**)&vth, g_vth);   cudaGetSymbolAddress((void**)&vtl, g_vtl);
    cudaGetSymbolAddress((void**)&avh, g_avh);   cudaGetSymbolAddress((void**)&avl, g_avl);
    cudaGetSymbolAddress((void**)&atth, g_atth); cudaGetSymbolAddress((void**)&attl, g_attl);
    cudaGetSymbolAddress((void**)&woh, g_woh);   cudaGetSymbolAddress((void**)&wol, g_wol);

    constexpr int SMEM128 = 2 * (2 * 128 * SMM_STRIDE * 2 + 2 * 128 * SMM_STRIDE * 2); // 81920
    constexpr int SMEM64  = 2 * (2 * 128 * SMM_STRIDE * 2 + 2 * 64 * SMM_STRIDE * 2);  // 61440
    cudaFuncSetAttribute(mm3_kernel<128, true>,  cudaFuncAttributeMaxDynamicSharedMemorySize, SMEM128);
    cudaFuncSetAttribute(mm3_kernel<128, false>, cudaFuncAttributeMaxDynamicSharedMemorySize, SMEM128);
    cudaFuncSetAttribute(mm3_kernel<64, true>,   cudaFuncAttributeMaxDynamicSharedMemorySize, SMEM64);

    const size_t SDM = (size_t)SEQ * DM;
    const size_t SS  = (size_t)SEQ * SEQ;

    // ---- input splits (1 launch, 8 segments) ----
    split8_kernel<<<dim3((int)(ACT / 4 / 256), 8), 256>>>(
        y, x, Wq, Wk, Wv, Wo, bq, bk, bv,
        acth, actl, wh3, wl3, woh, wol, bqkv);

    // ---- fused QKV projections: one launch, grid.z = 3 ----
    mm3_kernel<128, true><<<dim3(DM / 128, MR / 128, 3), 256, SMEM128>>>(
        acth, actl, 0, ACT, DM,
        wh3, wl3, 0, WSZ, DM,
        bqkv, DM,
        nullptr, qkvh, qkvl, 0, ACT, DM, DM, 1.f);

    // ---- v transpose (bf16); v = slice 2 of qkv ----
    transpose_v_kernel<<<dim3(SEQ / 64, NB * NHEAD), 256>>>(
        qkvh + 2 * ACT, qkvl + 2 * ACT, vth, vtl);

    // ---- scores: s[b,h] = 0.125 * q_bh @ k_bh^T  (K=64) ----
    mm3_kernel<128, false><<<dim3(SEQ / 128, SEQ / 128, NB * NHEAD), 256, SMEM128>>>(
        qkvh, qkvl, SDM, (size_t)HDIM, DM,
        qkvh + ACT, qkvl + ACT, SDM, (size_t)HDIM, DM,
        nullptr, 0,
        sc, nullptr, nullptr, (size_t)NHEAD * SS, SS, SEQ, HDIM, 0.125f);

    // ---- softmax + batch-sum -> bf16 hi/lo att ----
    softmax_sum_kernel<<<NHEAD * SEQ, 256>>>(sc, mask, atth, attl);

    // ---- AV: av[b,:,h*64+d] = att_h @ vt_bh^T  (N=64, K=1024), split out ----
    mm3_kernel<64, true><<<dim3(1, SEQ / 128, NB * NHEAD), 256, SMEM64>>>(
        atth, attl, 0, SS, SEQ,
        vth, vtl, (size_t)NHEAD * HDIM * SEQ, (size_t)HDIM * SEQ, SEQ,
        nullptr, 0,
        nullptr, avh, avl, SDM, (size_t)HDIM, DM, SEQ, 1.f);

    // ---- output projection (fp32 out + bias) ----
    mm3_kernel<128, false><<<dim3(DM / 128, MR / 128, 1), 256, SMEM128>>>(
        avh, avl, 0, 0, DM, woh, wol, 0, 0, DM,
        bo, 0,
        out, nullptr, nullptr, 0, 0, DM, DM, 1.f);
}

// round 16
// speedup vs baseline: 1.2501x; 1.0228x over previous
#include <cuda_runtime.h>
#include <cuda_bf16.h>
#include <cuda_fp16.h>
#include <math.h>
#include <stdint.h>

// Problem constants
constexpr int SEQ   = 1024;
constexpr int DM    = 1024;
constexpr int NHEAD = 16;
constexpr int HDIM  = 64;
constexpr int NB    = 4;
constexpr int MR    = NB * SEQ;

constexpr size_t ACT = (size_t)MR * DM;   // one activation slice
constexpr size_t WSZ = (size_t)DM * DM;   // one weight slice

// ---------------- scratch (device globals; no allocation allowed) ----------
__device__ __half g_s [(size_t)NB * NHEAD * SEQ * SEQ];   // fp16 scores (b,h,q,j)
__device__ float g_bqkv[3 * DM];                          // bq|bk|bv

__device__ __nv_bfloat16 g_acth[3 * ACT];   // y | x | x  (hi)
__device__ __nv_bfloat16 g_actl[3 * ACT];
__device__ __nv_bfloat16 g_wh3[3 * WSZ];    // wq | wk | wv (hi)
__device__ __nv_bfloat16 g_wl3[3 * WSZ];
__device__ __nv_bfloat16 g_qkvh[3 * ACT];   // q | k | v (hi)
__device__ __nv_bfloat16 g_qkvl[3 * ACT];
__device__ __nv_bfloat16 g_vth[(size_t)MR * DM];   // v^T per (b,h): [b][h][d][j]
__device__ __nv_bfloat16 g_vtl[(size_t)MR * DM];
__device__ __nv_bfloat16 g_avh[(size_t)MR * DM];
__device__ __nv_bfloat16 g_avl[(size_t)MR * DM];
__device__ __nv_bfloat16 g_atth[(size_t)NHEAD * SEQ * SEQ];
__device__ __nv_bfloat16 g_attl[(size_t)NHEAD * SEQ * SEQ];
__device__ __nv_bfloat16 g_woh[WSZ];
__device__ __nv_bfloat16 g_wol[WSZ];

// ===========================================================================
// helpers
// ===========================================================================
__device__ __forceinline__ uint32_t smem_u32(const void* p) {
    uint32_t r;
    asm("{ .reg .u64 t; cvta.to.shared.u64 t, %1; cvt.u32.u64 %0, t; }"
        : "=r"(r) : "l"(p));
    return r;
}
__device__ __forceinline__ void cp16(uint32_t dst, const void* src) {
    asm volatile("cp.async.cg.shared.global [%0], [%1], 16;" :: "r"(dst), "l"(src));
}
__device__ __forceinline__ void cp_commit() {
    asm volatile("cp.async.commit_group;" ::: "memory");
}
template <int N>
__device__ __forceinline__ void cp_wait() {
    asm volatile("cp.async.wait_group %0;" :: "n"(N) : "memory");
}
__device__ __forceinline__ void ldsm_x4(uint32_t* r, uint32_t addr) {
    asm volatile("ldmatrix.sync.aligned.m8n8.x4.shared.b16 {%0,%1,%2,%3}, [%4];"
        : "=r"(r[0]), "=r"(r[1]), "=r"(r[2]), "=r"(r[3]) : "r"(addr));
}
__device__ __forceinline__ void mma16816(
    float* d, const uint32_t* a, const uint32_t* b)
{
    asm volatile(
        "mma.sync.aligned.m16n8k16.row.col.f32.bf16.bf16.f32 "
        "{%0,%1,%2,%3}, {%4,%5,%6,%7}, {%8,%9}, {%0,%1,%2,%3};"
        : "+f"(d[0]), "+f"(d[1]), "+f"(d[2]), "+f"(d[3])
        : "r"(a[0]), "r"(a[1]), "r"(a[2]), "r"(a[3]), "r"(b[0]), "r"(b[1]));
}

// ===========================================================================
// input splits into sliced buffers (1 launch, grid.y = 8 segments)
// ===========================================================================
__global__ __launch_bounds__(256) void split8_kernel(
    const float* __restrict__ y,  const float* __restrict__ x,
    const float* __restrict__ wq, const float* __restrict__ wk,
    const float* __restrict__ wv, const float* __restrict__ wo,
    const float* __restrict__ bq, const float* __restrict__ bk,
    const float* __restrict__ bv,
    __nv_bfloat16* acth, __nv_bfloat16* actl,
    __nv_bfloat16* wh3,  __nv_bfloat16* wl3,
    __nv_bfloat16* woh,  __nv_bfloat16* wol,
    float* bqkv)
{
    const int seg = blockIdx.y;
    const int tid = threadIdx.x;

    if (seg == 7) {
        if (blockIdx.x == 0 && tid < 256) {
            ((float4*)bqkv)[tid]       = ((const float4*)bq)[tid];
            ((float4*)bqkv)[tid + 256] = ((const float4*)bk)[tid];
            ((float4*)bqkv)[tid + 512] = ((const float4*)bv)[tid];
        }
        return;
    }

    const float* in; __nv_bfloat16 *hi, *lo; int n4;
    if (seg < 3) {
        in = (seg == 0) ? y : x;
        hi = acth + (size_t)seg * ACT;
        lo = actl + (size_t)seg * ACT;
        n4 = (int)(ACT / 4);
    } else if (seg < 6) {
        in = (seg == 3) ? wq : (seg == 4) ? wk : wv;
        hi = wh3 + (size_t)(seg - 3) * WSZ;
        lo = wl3 + (size_t)(seg - 3) * WSZ;
        n4 = (int)(WSZ / 4);
    } else {
        in = wo; hi = woh; lo = wol; n4 = (int)(WSZ / 4);
    }

    int i = blockIdx.x * blockDim.x + tid;
    if (i >= n4) return;
    float4 v = ((const float4*)in)[i];
    __nv_bfloat16 h0 = __float2bfloat16(v.x);
    __nv_bfloat16 h1 = __float2bfloat16(v.y);
    __nv_bfloat16 h2 = __float2bfloat16(v.z);
    __nv_bfloat16 h3 = __float2bfloat16(v.w);
    ushort4 H, L;
    H.x = __bfloat16_as_ushort(h0); H.y = __bfloat16_as_ushort(h1);
    H.z = __bfloat16_as_ushort(h2); H.w = __bfloat16_as_ushort(h3);
    L.x = __bfloat16_as_ushort(__float2bfloat16(v.x - __bfloat162float(h0)));
    L.y = __bfloat16_as_ushort(__float2bfloat16(v.y - __bfloat162float(h1)));
    L.z = __bfloat16_as_ushort(__float2bfloat16(v.z - __bfloat162float(h2)));
    L.w = __bfloat16_as_ushort(__float2bfloat16(v.w - __bfloat162float(h3)));
    ((ushort4*)hi)[i] = H;
    ((ushort4*)lo)[i] = L;
}

// ===========================================================================
// bf16 transpose of v hi/lo:  vt[b][h][d][j] = v[b*S+j][h*64+d]
// ===========================================================================
__global__ __launch_bounds__(256) void transpose_v_kernel(
    const __nv_bfloat16* __restrict__ vh, const __nv_bfloat16* __restrict__ vl,
    __nv_bfloat16* __restrict__ vth, __nv_bfloat16* __restrict__ vtl)
{
    __shared__ uint16_t th[64][72];
    __shared__ uint16_t tl[64][72];
    const int bh = blockIdx.y;
    const int b  = bh >> 4;
    const int h  = bh & 15;
    const int j0 = blockIdx.x * 64;
    const int tid = threadIdx.x;

#pragma unroll
    for (int i = 0; i < 4; i++) {
        int idx = tid + i * 256;
        int j   = idx >> 4;
        int dq  = (idx & 15) * 4;
        size_t off = (size_t)(b * SEQ + j0 + j) * DM + h * HDIM + dq;
        ushort4 a = *(const ushort4*)((const uint16_t*)vh + off);
        ushort4 c = *(const ushort4*)((const uint16_t*)vl + off);
        th[dq + 0][j] = a.x; th[dq + 1][j] = a.y; th[dq + 2][j] = a.z; th[dq + 3][j] = a.w;
        tl[dq + 0][j] = c.x; tl[dq + 1][j] = c.y; tl[dq + 2][j] = c.z; tl[dq + 3][j] = c.w;
    }
    __syncthreads();

    const int d  = tid >> 2;
    const int jq = (tid & 3) * 16;
    uint16_t* oh = (uint16_t*)vth + ((size_t)bh * HDIM + d) * SEQ + j0 + jq;
    uint16_t* ol = (uint16_t*)vtl + ((size_t)bh * HDIM + d) * SEQ + j0 + jq;
#pragma unroll
    for (int c = 0; c < 4; c++) {
        ushort4 A, B;
        A.x = th[d][jq + c * 4 + 0]; A.y = th[d][jq + c * 4 + 1];
        A.z = th[d][jq + c * 4 + 2]; A.w = th[d][jq + c * 4 + 3];
        B.x = tl[d][jq + c * 4 + 0]; B.y = tl[d][jq + c * 4 + 1];
        B.z = tl[d][jq + c * 4 + 2]; B.w = tl[d][jq + c * 4 + 3];
        *(ushort4*)(oh + c * 4) = A;
        *(ushort4*)(ol + c * 4) = B;
    }
}

// ===========================================================================
// Generic bf16x3 compensated GEMM, ldmatrix fragments, cp.async 2-stage,
// single-sync mainloop. Output modes: 0 = fp32, 1 = bf16 hi/lo, 2 = fp16.
// ===========================================================================
#define SMM_STRIDE 40   // 32 k elems + 8 pad (bf16)

template <int NT, int OMODE>
__global__ __launch_bounds__(256, 2) void mm3_kernel(
    const __nv_bfloat16* __restrict__ Ah, const __nv_bfloat16* __restrict__ Al,
    size_t asb, size_t ash, int lda,
    const __nv_bfloat16* __restrict__ Wh, const __nv_bfloat16* __restrict__ Wl,
    size_t wsb, size_t wsh, int ldw,
    const float* __restrict__ bias, int bsh,
    float* __restrict__ C, __nv_bfloat16* __restrict__ Ch, __nv_bfloat16* __restrict__ Cl,
    __half* __restrict__ Chalf,
    size_t csb, size_t csh, int ldc,
    int K, float scale)
{
    constexpr int NATOMS  = NT / 16;
    constexpr int A_BYTES = 128 * SMM_STRIDE * 2;
    constexpr int W_BYTES = NT * SMM_STRIDE * 2;
    constexpr int STAGE   = 2 * A_BYTES + 2 * W_BYTES;

    extern __shared__ char smem[];
    const uint32_t sbase = smem_u32(smem);

    const int tid  = threadIdx.x;
    const int wid  = tid >> 5;
    const int lane = tid & 31;
    const int gid  = lane >> 2;
    const int tig  = lane & 3;
    const int wm   = wid & 3;
    const int wn   = wid >> 2;
    const int m0   = blockIdx.y * 128;
    const int n0   = blockIdx.x * NT;
    const int z    = blockIdx.z;
    const int zb   = z >> 4;
    const int zh   = z & 15;

    const __nv_bfloat16* pAh = Ah + (size_t)zb * asb + (size_t)zh * ash;
    const __nv_bfloat16* pAl = Al + (size_t)zb * asb + (size_t)zh * ash;
    const __nv_bfloat16* pWh = Wh + (size_t)zb * wsb + (size_t)zh * wsh;
    const __nv_bfloat16* pWl = Wl + (size_t)zb * wsb + (size_t)zh * wsh;

    const int a_r = lane & 15;
    const int a_c = (lane >> 4) << 3;
    const int w_r = (lane & 7) + ((lane & 16) >> 1);
    const int w_c = ((lane >> 3) & 1) << 3;

    float acc[2][NATOMS][4];
#pragma unroll
    for (int i = 0; i < 2; i++)
#pragma unroll
        for (int j = 0; j < NATOMS; j++)
#pragma unroll
            for (int c = 0; c < 4; c++) acc[i][j][c] = 0.f;

    const int nk = K >> 5;

    auto load_stage = [&](int s, int k0) {
        uint32_t st = sbase + s * STAGE;
#pragma unroll
        for (int i = 0; i < 2; i++) {
            int idx = tid + i * 256;
            int row = idx >> 2;
            int kq  = idx & 3;
            uint32_t doff = (row * SMM_STRIDE + kq * 8) * 2;
            cp16(st + doff,           pAh + (size_t)(m0 + row) * lda + k0 + kq * 8);
            cp16(st + A_BYTES + doff, pAl + (size_t)(m0 + row) * lda + k0 + kq * 8);
        }
#pragma unroll
        for (int i = 0; i < (NT == 128 ? 2 : 1); i++) {
            int idx = tid + i * 256;
            int row = idx >> 2;
            int kq  = idx & 3;
            uint32_t doff = (row * SMM_STRIDE + kq * 8) * 2;
            cp16(st + 2 * A_BYTES + doff,           pWh + (size_t)(n0 + row) * ldw + k0 + kq * 8);
            cp16(st + 2 * A_BYTES + W_BYTES + doff, pWl + (size_t)(n0 + row) * ldw + k0 + kq * 8);
        }
    };

    load_stage(0, 0);
    cp_commit();

    for (int c0 = 0; c0 < nk; c0++) {
        cp_wait<0>();
        __syncthreads();
        if (c0 + 1 < nk) { load_stage((c0 + 1) & 1, (c0 + 1) * 32); cp_commit(); }

        uint32_t st  = sbase + (c0 & 1) * STAGE;
        uint32_t sAh = st;
        uint32_t sAl = st + A_BYTES;
        uint32_t sWh = st + 2 * A_BYTES;
        uint32_t sWl = st + 2 * A_BYTES + W_BYTES;

#pragma unroll
        for (int ks = 0; ks < 2; ks++) {
            const int cb = ks * 16;
            uint32_t afh[2][4], afl[2][4], wf[NATOMS][2];

#pragma unroll
            for (int i = 0; i < 2; i++) {
                int r = wm * 32 + i * 16 + a_r;
                ldsm_x4(afh[i], sAh + (r * SMM_STRIDE + cb + a_c) * 2);
            }
#pragma unroll
            for (int jp = 0; jp < NATOMS / 2; jp++) {
                int n = wn * (NT / 2) + jp * 16 + w_r;
                ldsm_x4(&wf[2 * jp][0], sWh + (n * SMM_STRIDE + cb + w_c) * 2);
            }
#pragma unroll
            for (int i = 0; i < 2; i++)
#pragma unroll
                for (int j = 0; j < NATOMS; j++) mma16816(acc[i][j], afh[i], wf[j]);

#pragma unroll
            for (int i = 0; i < 2; i++) {
                int r = wm * 32 + i * 16 + a_r;
                ldsm_x4(afl[i], sAl + (r * SMM_STRIDE + cb + a_c) * 2);
            }
#pragma unroll
            for (int i = 0; i < 2; i++)
#pragma unroll
                for (int j = 0; j < NATOMS; j++) mma16816(acc[i][j], afl[i], wf[j]);

#pragma unroll
            for (int jp = 0; jp < NATOMS / 2; jp++) {
                int n = wn * (NT / 2) + jp * 16 + w_r;
                ldsm_x4(&wf[2 * jp][0], sWl + (n * SMM_STRIDE + cb + w_c) * 2);
            }
#pragma unroll
            for (int i = 0; i < 2; i++)
#pragma unroll
                for (int j = 0; j < NATOMS; j++) mma16816(acc[i][j], afh[i], wf[j]);
        }
    }

    // ---- epilogue (register-private; no barrier needed) ----
#pragma unroll
    for (int i = 0; i < 2; i++) {
        int row = m0 + wm * 32 + i * 16 + gid;
#pragma unroll
        for (int j = 0; j < NATOMS; j++) {
            int col = n0 + wn * (NT / 2) + j * 8 + tig * 2;
            float b0 = bias ? bias[zh * bsh + col] : 0.f;
            float b1 = bias ? bias[zh * bsh + col + 1] : 0.f;
            float f0 = acc[i][j][0] * scale + b0;
            float f1 = acc[i][j][1] * scale + b1;
            float f2 = acc[i][j][2] * scale + b0;
            float f3 = acc[i][j][3] * scale + b1;
            if (OMODE == 1) {
                uint16_t* pH = (uint16_t*)Ch + (size_t)zb * csb + (size_t)zh * csh;
                uint16_t* pL = (uint16_t*)Cl + (size_t)zb * csb + (size_t)zh * csh;
                __nv_bfloat16 h0 = __float2bfloat16(f0), h1 = __float2bfloat16(f1);
                __nv_bfloat16 h2 = __float2bfloat16(f2), h3 = __float2bfloat16(f3);
                ushort2 H0 = {__bfloat16_as_ushort(h0), __bfloat16_as_ushort(h1)};
                ushort2 H1 = {__bfloat16_as_ushort(h2), __bfloat16_as_ushort(h3)};
                ushort2 L0 = {__bfloat16_as_ushort(__float2bfloat16(f0 - __bfloat162float(h0))),
                              __bfloat16_as_ushort(__float2bfloat16(f1 - __bfloat162float(h1)))};
                ushort2 L1 = {__bfloat16_as_ushort(__float2bfloat16(f2 - __bfloat162float(h2))),
                              __bfloat16_as_ushort(__float2bfloat16(f3 - __bfloat162float(h3)))};
                *(ushort2*)(pH + (size_t)row * ldc + col) = H0;
                *(ushort2*)(pH + (size_t)(row + 8) * ldc + col) = H1;
                *(ushort2*)(pL + (size_t)row * ldc + col) = L0;
                *(ushort2*)(pL + (size_t)(row + 8) * ldc + col) = L1;
            } else if (OMODE == 2) {
                __half* pC = Chalf + (size_t)zb * csb + (size_t)zh * csh;
                __half2 v0 = __floats2half2_rn(f0, f1);
                __half2 v1 = __floats2half2_rn(f2, f3);
                *(__half2*)(pC + (size_t)row * ldc + col) = v0;
                *(__half2*)(pC + (size_t)(row + 8) * ldc + col) = v1;
            } else {
                float* pC = C + (size_t)zb * csb + (size_t)zh * csh;
                *(float2*)(pC + (size_t)row * ldc + col) = make_float2(f0, f1);
                *(float2*)(pC + (size_t)(row + 8) * ldc + col) = make_float2(f2, f3);
            }
        }
    }
}

// ===========================================================================
// Softmax over j (+mask), NaN->0, sum over batch; reads fp16 scores,
// emits bf16 hi/lo att.
// ===========================================================================
__global__ __launch_bounds__(256) void softmax_sum_kernel(
    const __half* __restrict__ s, const float* __restrict__ mask,
    __nv_bfloat16* __restrict__ atth, __nv_bfloat16* __restrict__ attl)
{
    __shared__ float red[8];

    const int h   = blockIdx.x >> 10;
    const int qi  = blockIdx.x & 1023;
    const int tid = threadIdx.x;
    const int lane = tid & 31;
    const int warp = tid >> 5;

    float mv[4];
#pragma unroll
    for (int u = 0; u < 4; u++) mv[u] = mask[(size_t)qi * SEQ + tid + u * 256];

    float facc[4] = {0.f, 0.f, 0.f, 0.f};

    for (int b = 0; b < NB; b++) {
        const __half* srow = s + (((size_t)(b * NHEAD + h)) * SEQ + qi) * SEQ;
        float rv[4];
        float m = -INFINITY;
#pragma unroll
        for (int u = 0; u < 4; u++) {
            rv[u] = __half2float(srow[tid + u * 256]) + mv[u];
            m = fmaxf(m, rv[u]);
        }
#pragma unroll
        for (int o = 16; o > 0; o >>= 1) m = fmaxf(m, __shfl_xor_sync(0xffffffffu, m, o));
        __syncthreads();
        if (lane == 0) red[warp] = m;
        __syncthreads();
        m = red[0];
#pragma unroll
        for (int w = 1; w < 8; w++) m = fmaxf(m, red[w]);

        float ssum = 0.f;
#pragma unroll
        for (int u = 0; u < 4; u++) {
            rv[u] = __expf(rv[u] - m);
            ssum += rv[u];
        }
#pragma unroll
        for (int o = 16; o > 0; o >>= 1) ssum += __shfl_xor_sync(0xffffffffu, ssum, o);
        __syncthreads();
        if (lane == 0) red[warp] = ssum;
        __syncthreads();
        ssum = 0.f;
#pragma unroll
        for (int w = 0; w < 8; w++) ssum += red[w];

        if (ssum > 0.f && isfinite(ssum)) {
            float inv = 1.f / ssum;
#pragma unroll
            for (int u = 0; u < 4; u++) facc[u] += rv[u] * inv;
        }
    }

    size_t rowoff = ((size_t)h * SEQ + qi) * SEQ;
#pragma unroll
    for (int u = 0; u < 4; u++) {
        float f = facc[u];
        __nv_bfloat16 hi = __float2bfloat16(f);
        atth[rowoff + tid + u * 256] = hi;
        attl[rowoff + tid + u * 256] = __float2bfloat16(f - __bfloat162float(hi));
    }
}

// ===========================================================================
extern "C" void kernel_launch(void* const* d_in, const int* in_sizes, int n_in,
                              void* d_out, int out_size)
{
    const float* x    = (const float*)d_in[0];
    const float* y    = (const float*)d_in[1];
    const float* mask = (const float*)d_in[2];
    const float* Wq   = (const float*)d_in[3];
    const float* bq   = (const float*)d_in[4];
    const float* Wk   = (const float*)d_in[5];
    const float* bk   = (const float*)d_in[6];
    const float* Wv   = (const float*)d_in[7];
    const float* bv   = (const float*)d_in[8];
    const float* Wo   = (const float*)d_in[9];
    const float* bo   = (const float*)d_in[10];
    float* out = (float*)d_out;

    __half* sc;
    float* bqkv;
    cudaGetSymbolAddress((void**)&sc,   g_s);
    cudaGetSymbolAddress((void**)&bqkv, g_bqkv);

    __nv_bfloat16 *acth, *actl, *wh3, *wl3, *qkvh, *qkvl;
    __nv_bfloat16 *vth, *vtl, *avh, *avl, *atth, *attl, *woh, *wol;
    cudaGetSymbolAddress((void**)&acth, g_acth); cudaGetSymbolAddress((void**)&actl, g_actl);
    cudaGetSymbolAddress((void**)&wh3, g_wh3);   cudaGetSymbolAddress((void**)&wl3, g_wl3);
    cudaGetSymbolAddress((void**)&qkvh, g_qkvh); cudaGetSymbolAddress((void**)&qkvl, g_qkvl);
    cudaGetSymbolAddress((void**)&vth, g_vth);   cudaGetSymbolAddress((void**)&vtl, g_vtl);
    cudaGetSymbolAddress((void**)&avh, g_avh);   cudaGetSymbolAddress((void**)&avl, g_avl);
    cudaGetSymbolAddress((void**)&atth, g_atth); cudaGetSymbolAddress((void**)&attl, g_attl);
    cudaGetSymbolAddress((void**)&woh, g_woh);   cudaGetSymbolAddress((void**)&wol, g_wol);

    constexpr int SMEM128 = 2 * (2 * 128 * SMM_STRIDE * 2 + 2 * 128 * SMM_STRIDE * 2); // 81920
    constexpr int SMEM64  = 2 * (2 * 128 * SMM_STRIDE * 2 + 2 * 64 * SMM_STRIDE * 2);  // 61440
    cudaFuncSetAttribute(mm3_kernel<128, 1>, cudaFuncAttributeMaxDynamicSharedMemorySize, SMEM128);
    cudaFuncSetAttribute(mm3_kernel<128, 0>, cudaFuncAttributeMaxDynamicSharedMemorySize, SMEM128);
    cudaFuncSetAttribute(mm3_kernel<128, 2>, cudaFuncAttributeMaxDynamicSharedMemorySize, SMEM128);
    cudaFuncSetAttribute(mm3_kernel<64, 1>,  cudaFuncAttributeMaxDynamicSharedMemorySize, SMEM64);

    const size_t SDM = (size_t)SEQ * DM;
    const size_t SS  = (size_t)SEQ * SEQ;

    // ---- input splits (1 launch, 8 segments) ----
    split8_kernel<<<dim3((int)(ACT / 4 / 256), 8), 256>>>(
        y, x, Wq, Wk, Wv, Wo, bq, bk, bv,
        acth, actl, wh3, wl3, woh, wol, bqkv);

    // ---- fused QKV projections: one launch, grid.z = 3 ----
    mm3_kernel<128, 1><<<dim3(DM / 128, MR / 128, 3), 256, SMEM128>>>(
        acth, actl, 0, ACT, DM,
        wh3, wl3, 0, WSZ, DM,
        bqkv, DM,
        nullptr, qkvh, qkvl, nullptr, 0, ACT, DM, DM, 1.f);

    // ---- v transpose (bf16); v = slice 2 of qkv ----
    transpose_v_kernel<<<dim3(SEQ / 64, NB * NHEAD), 256>>>(
        qkvh + 2 * ACT, qkvl + 2 * ACT, vth, vtl);

    // ---- scores: s[b,h] = 0.125 * q_bh @ k_bh^T  (K=64), fp16 out ----
    mm3_kernel<128, 2><<<dim3(SEQ / 128, SEQ / 128, NB * NHEAD), 256, SMEM128>>>(
        qkvh, qkvl, SDM, (size_t)HDIM, DM,
        qkvh + ACT, qkvl + ACT, SDM, (size_t)HDIM, DM,
        nullptr, 0,
        nullptr, nullptr, nullptr, sc, (size_t)NHEAD * SS, SS, SEQ, HDIM, 0.125f);

    // ---- softmax + batch-sum -> bf16 hi/lo att ----
    softmax_sum_kernel<<<NHEAD * SEQ, 256>>>(sc, mask, atth, attl);

    // ---- AV: av[b,:,h*64+d] = att_h @ vt_bh^T  (N=64, K=1024), split out ----
    mm3_kernel<64, 1><<<dim3(1, SEQ / 128, NB * NHEAD), 256, SMEM64>>>(
        atth, attl, 0, SS, SEQ,
        vth, vtl, (size_t)NHEAD * HDIM * SEQ, (size_t)HDIM * SEQ, SEQ,
        nullptr, 0,
        nullptr, avh, avl, nullptr, SDM, (size_t)HDIM, DM, SEQ, 1.f);

    // ---- output projection (fp32 out + bias) ----
    mm3_kernel<128, 0><<<dim3(DM / 128, MR / 128, 1), 256, SMEM128>>>(
        avh, avl, 0, 0, DM, woh, wol, 0, 0, DM,
        bo, 0,
        out, nullptr, nullptr, nullptr, 0, 0, DM, DM, 1.f);
}